// round 14
// baseline (speedup 1.0000x reference)
#include <cuda_runtime.h>
#include <cuda_bf16.h>
#include <math.h>
#include <stdint.h>

// Problem dims
#define BB 32
#define SS 2048
#define CC 1536
#define NN 200
#define KSEL 128
#define NCAND 160             // candidate pool per batch (32-rank margin)
#define CPB 40                // candidates per exact block (4 blocks/batch)
#define TOT (BB * SS)         // 65536 tokens

#define NPAD 208              // class dim: 7/7/6/6 n-tiles across 4 N-warps
#define NCH16 96              // K chunks of 16
#define NCH32 48              // K chunks of 32
#define WCH1 (NPAD * 8)       // u32 per k16 chunk of swizzled W = 1664

// Scratch (no cudaMalloc allowed)
__device__ float g_logits[(size_t)NN * TOT];   // [n][token], 52.4 MB
__device__ float g_lse[TOT];                   // per-token logsumexp
__device__ float g_msum[BB * NN];              // per-(b,n) logit sums (atomic)
__device__ int   g_maxid[BB];
__device__ int   g_cand[BB * NCAND];           // candidate token indices
__device__ float g_cscore[BB * NCAND];         // exact scores of candidates
__device__ int   g_topk[BB * KSEL];
__device__ __align__(16) uint32_t g_wswz[NCH16 * WCH1];

__device__ __forceinline__ uint32_t pack2bf(float a, float b) {
    __nv_bfloat162 p = __float22bfloat162_rn(make_float2(a, b));
    return *reinterpret_cast<uint32_t*>(&p);
}

// ---------------------------------------------------------------------------
// K-1: W -> bf16, fragment-swizzled in global (proven). Also zeroes g_msum.
// ---------------------------------------------------------------------------
__global__ void wconv_kernel(const float* __restrict__ W) {
    int i = blockIdx.x * blockDim.x + threadIdx.x;
    if (i < BB * NN) g_msum[i] = 0.f;
    if (i >= NCH16 * WCH1) return;
    int c = i / WCH1;
    int rem = i % WCH1;
    int n = rem >> 3, p = rem & 7;
    float v0 = 0.f, v1 = 0.f;
    if (n < NN) {
        int k = c * 16 + 2 * p;
        v0 = W[(size_t)n * CC + k];
        v1 = W[(size_t)n * CC + k + 1];
    }
    int w = (p & 3) * 2 + (p >> 2);
    g_wswz[c * WCH1 + n * 8 + w] = pack2bf(v0, v1);
}

// ---------------------------------------------------------------------------
// K2: APPROX logits GEMM (register MMA, bf16, k32 chunks, cp.async W).
// N=208 (26 n-tiles): warps mapped mw=warp&1, nw=warp>>1 so each SMSP gets
// one 7-tile warp + one 6-tile warp (balanced 104 HMMA/SMSP/chunk, -7%).
// Everything else identical to the proven round-11/13 config.
// ---------------------------------------------------------------------------
#define MMA_BF16(d, a, b0_, b1_)                                            \
    asm volatile(                                                           \
        "mma.sync.aligned.m16n8k16.row.col.f32.bf16.bf16.f32 "              \
        "{%0,%1,%2,%3}, {%4,%5,%6,%7}, {%8,%9}, {%0,%1,%2,%3};"             \
        : "+f"(d[0]), "+f"(d[1]), "+f"(d[2]), "+f"(d[3])                    \
        : "r"(a[0]), "r"(a[1]), "r"(a[2]), "r"(a[3]), "r"(b0_), "r"(b1_))

#define XSBUF 2048            // u32 per x stage: [2 half][128][8]
#define WSBUF (2 * WCH1)      // u32 per W stage: [2 half][208][8] = 3328
#define SMEMB ((2 * XSBUF + 3 * WSBUF + NPAD + 2 * 512) * 4)

__global__ __launch_bounds__(256, 1)
void score_mma_kernel(const float* __restrict__ x,
                      const float* __restrict__ bias) {
    extern __shared__ uint32_t sm[];
    uint32_t* xs = sm;                        // [2 buf][2 half][128][8]
    uint32_t* ws = sm + 2 * XSBUF;            // [3 buf][2 half][208][8]
    float* bias_s = (float*)(ws + 3 * WSBUF); // [208]
    float* p_mx = bias_s + NPAD;              // [128][4]
    float* p_se = p_mx + 512;

    int tid  = threadIdx.x;
    int warp = tid >> 5, lane = tid & 31;
    int gid  = lane >> 2, tig = lane & 3;
    int mw   = warp & 1;                      // SMSP-balanced mapping
    int nw   = warp >> 1;                     // nw 0..3
    int ntc   = (nw < 2) ? 7 : 6;             // n-tiles this warp
    int nbase = (nw < 2) ? nw * 56 : 112 + (nw - 2) * 48;
    int token0 = blockIdx.x * 128;            // 16 blocks per batch
    int b = token0 >> 11;

    for (int n = tid; n < NPAD; n += 256)
        bias_s[n] = (n < NN) ? __ldg(&bias[n]) : -1e30f;

    float acc[4][7][4];
    #pragma unroll
    for (int mt = 0; mt < 4; mt++)
        #pragma unroll
        for (int nt = 0; nt < 7; nt++)
            #pragma unroll
            for (int r = 0; r < 4; r++) acc[mt][nt][r] = 0.f;

    const float* xbase = x + (size_t)token0 * CC;

    int xrow = tid >> 3;            // 0..31; tasks at rows +0,+32,+64,+96
    int xp   = tid & 7;
    int xw   = (xp & 3) * 2 + (xp >> 2);
    float2 rx[4][2];                // [task][half]

    auto ldx = [&](int c) {
        #pragma unroll
        for (int t = 0; t < 4; t++) {
            const float* p = xbase + (size_t)(xrow + 32 * t) * CC + c * 32 + 2 * xp;
            rx[t][0] = *(const float2*)p;
            rx[t][1] = *(const float2*)(p + 16);
        }
    };
    auto stx = [&](int xb) {
        uint32_t* base = xs + xb * XSBUF;
        #pragma unroll
        for (int t = 0; t < 4; t++) {
            int r = xrow + 32 * t;
            base[0 * 1024 + r * 8 + xw] = pack2bf(rx[t][0].x, rx[t][0].y);
            base[1 * 1024 + r * 8 + xw] = pack2bf(rx[t][1].x, rx[t][1].y);
        }
    };
    auto cpW = [&](int c, int wb) {
        const uint4* src = (const uint4*)(g_wswz + (size_t)(2 * c) * WCH1);
        uint32_t dst = (uint32_t)__cvta_generic_to_shared(ws + wb * WSBUF);
        #pragma unroll
        for (int r = 0; r < 3; r++) {
            int e = tid + r * 256;
            asm volatile("cp.async.cg.shared.global [%0], [%1], 16;"
                         :: "r"(dst + e * 16), "l"(src + e));
        }
        if (tid < 64) {
            int e = tid + 768;                 // 832 uint4 total (3328 u32)
            asm volatile("cp.async.cg.shared.global [%0], [%1], 16;"
                         :: "r"(dst + e * 16), "l"(src + e));
        }
    };

    cpW(0, 0); asm volatile("cp.async.commit_group;");
    cpW(1, 1); asm volatile("cp.async.commit_group;");
    ldx(0); stx(0);
    ldx(1);
    asm volatile("cp.async.wait_group 1;");
    __syncthreads();

    for (int c = 0; c < NCH32; c++) {
        int xb = c & 1, wb = c % 3;
        const uint32_t* xsb = xs + xb * XSBUF;
        const uint32_t* wsb = ws + wb * WSBUF;

        #pragma unroll
        for (int h = 0; h < 2; h++) {
            uint32_t af[4][4];
            #pragma unroll
            for (int mt = 0; mt < 4; mt++) {
                int row0 = mw * 64 + mt * 16 + gid;
                const uint32_t* pa = xsb + h * 1024 + row0 * 8 + tig * 2;
                uint2 t0 = *(const uint2*)pa;
                uint2 t1 = *(const uint2*)(pa + 64);
                af[mt][0] = t0.x;  af[mt][2] = t0.y;
                af[mt][1] = t1.x;  af[mt][3] = t1.y;
            }
            #pragma unroll
            for (int nt = 0; nt < 7; nt++) {
                if (nt >= ntc) break;
                int nrow = nbase + nt * 8 + gid;
                uint2 B0 = *(const uint2*)(wsb + h * WCH1 + nrow * 8 + tig * 2);
                MMA_BF16(acc[0][nt], af[0], B0.x, B0.y);
                MMA_BF16(acc[1][nt], af[1], B0.x, B0.y);
                MMA_BF16(acc[2][nt], af[2], B0.x, B0.y);
                MMA_BF16(acc[3][nt], af[3], B0.x, B0.y);
            }
        }

        if (c + 1 < NCH32) {
            stx(xb ^ 1);
            if (c + 2 < NCH32) { ldx(c + 2); cpW(c + 2, (c + 2) % 3); }
            asm volatile("cp.async.commit_group;");
            asm volatile("cp.async.wait_group 1;");
            __syncthreads();
        }
    }

    // ---- bias add + logit store (transposed [n][token]) + fused class sums
    #pragma unroll
    for (int nt = 0; nt < 7; nt++) {
        if (nt >= ntc) break;
        int n0 = nbase + nt * 8 + tig * 2;
        float b0 = bias_s[n0], b1 = bias_s[n0 + 1];
        #pragma unroll
        for (int mt = 0; mt < 4; mt++) {
            acc[mt][nt][0] += b0; acc[mt][nt][1] += b1;
            acc[mt][nt][2] += b0; acc[mt][nt][3] += b1;
        }
        if (n0 < NN) {
            #pragma unroll
            for (int mt = 0; mt < 4; mt++) {
                int r0 = token0 + mw * 64 + mt * 16 + gid;
                g_logits[(size_t)n0 * TOT + r0]           = acc[mt][nt][0];
                g_logits[(size_t)(n0 + 1) * TOT + r0]     = acc[mt][nt][1];
                g_logits[(size_t)n0 * TOT + r0 + 8]       = acc[mt][nt][2];
                g_logits[(size_t)(n0 + 1) * TOT + r0 + 8] = acc[mt][nt][3];
            }
        }

        float s0 = 0.f, s1 = 0.f;
        #pragma unroll
        for (int mt = 0; mt < 4; mt++) {
            s0 += acc[mt][nt][0] + acc[mt][nt][2];
            s1 += acc[mt][nt][1] + acc[mt][nt][3];
        }
        #pragma unroll
        for (int o = 4; o <= 16; o <<= 1) {
            s0 += __shfl_xor_sync(0xffffffffu, s0, o);
            s1 += __shfl_xor_sync(0xffffffffu, s1, o);
        }
        if (gid == 0 && n0 < NN) {
            atomicAdd(&g_msum[b * NN + n0], s0);
            if (n0 + 1 < NN) atomicAdd(&g_msum[b * NN + n0 + 1], s1);
        }
    }

    #pragma unroll
    for (int mt = 0; mt < 4; mt++) {
        #pragma unroll
        for (int half = 0; half < 2; half++) {
            float mx = -1e30f;
            #pragma unroll
            for (int nt = 0; nt < 7; nt++) {
                if (nt >= ntc) break;
                mx = fmaxf(mx, fmaxf(acc[mt][nt][2 * half],
                                     acc[mt][nt][2 * half + 1]));
            }
            mx = fmaxf(mx, __shfl_xor_sync(0xffffffffu, mx, 1));
            mx = fmaxf(mx, __shfl_xor_sync(0xffffffffu, mx, 2));

            float se = 0.f;
            #pragma unroll
            for (int nt = 0; nt < 7; nt++) {
                if (nt >= ntc) break;
                se += expf(acc[mt][nt][2 * half] - mx)
                    + expf(acc[mt][nt][2 * half + 1] - mx);
            }
            se += __shfl_xor_sync(0xffffffffu, se, 1);
            se += __shfl_xor_sync(0xffffffffu, se, 2);

            if (tig == 0) {
                int row = mw * 64 + mt * 16 + half * 8 + gid;
                p_mx[row * 4 + nw] = mx;
                p_se[row * 4 + nw] = se;
            }
        }
    }
    __syncthreads();

    if (tid < 128) {
        float m0 = p_mx[tid * 4 + 0], m1 = p_mx[tid * 4 + 1];
        float m2 = p_mx[tid * 4 + 2], m3 = p_mx[tid * 4 + 3];
        float M = fmaxf(fmaxf(m0, m1), fmaxf(m2, m3));
        float se = p_se[tid * 4 + 0] * expf(m0 - M)
                 + p_se[tid * 4 + 1] * expf(m1 - M)
                 + p_se[tid * 4 + 2] * expf(m2 - M)
                 + p_se[tid * 4 + 3] * expf(m3 - M);
        g_lse[token0 + tid] = M + logf(se);
    }
}

// ---------------------------------------------------------------------------
// K3: per-batch argmax over the NN class sums.
// ---------------------------------------------------------------------------
__global__ void argmax2_kernel() {
    __shared__ float vals[256];
    __shared__ int   idxs[256];
    int b = blockIdx.x, n = threadIdx.x;
    vals[n] = (n < NN) ? g_msum[b * NN + n] : -INFINITY;
    idxs[n] = (n < NN) ? n : (1 << 30);
    __syncthreads();
    for (int o = 128; o > 0; o >>= 1) {
        if (n < o) {
            float v2 = vals[n + o]; int i2 = idxs[n + o];
            float v1 = vals[n];     int i1 = idxs[n];
            if (v2 > v1 || (v2 == v1 && i2 < i1)) { vals[n] = v2; idxs[n] = i2; }
        }
        __syncthreads();
    }
    if (n == 0) g_maxid[b] = idxs[0];
}

// ---------------------------------------------------------------------------
// K4: per-batch bitonic sort of 2048 approx scores -> top-160 candidates.
// ---------------------------------------------------------------------------
__global__ void cand_kernel() {
    __shared__ float s[SS];
    __shared__ int   si[SS];
    int b = blockIdx.x;
    int id = g_maxid[b];
    const float* lg = g_logits + (size_t)id * TOT + b * SS;
    const float* ls = g_lse + b * SS;
    for (int t = threadIdx.x; t < SS; t += blockDim.x) {
        s[t]  = lg[t] - ls[t];
        si[t] = t;
    }
    __syncthreads();
    for (int k = 2; k <= SS; k <<= 1) {
        for (int j = k >> 1; j > 0; j >>= 1) {
            for (int t = threadIdx.x; t < SS; t += blockDim.x) {
                int ixj = t ^ j;
                if (ixj > t) {
                    float a = s[t],  c = s[ixj];
                    int  ai = si[t], ci = si[ixj];
                    bool aBetter = (a > c) || (a == c && ai < ci);
                    bool descHere = ((t & k) == 0);
                    bool doSwap = descHere ? !aBetter : aBetter;
                    if (doSwap) {
                        s[t] = c;  s[ixj] = a;
                        si[t] = ci; si[ixj] = ai;
                    }
                }
            }
            __syncthreads();
        }
    }
    for (int t = threadIdx.x; t < NCAND; t += blockDim.x)
        g_cand[b * NCAND + t] = si[t];
}

// ---------------------------------------------------------------------------
// K5: EXACT rescore — proven fp32 math (identical [kk][*] layouts + fmaf
// chain), now with cp.async double-buffered tile fills (3-stage ring, the
// same proven pattern as score_mma's W path). 40 cand/block, 256 threads,
// uneven-balanced rows (warps 0-3: 3 rows, warps 4-7: 2 rows).
// ---------------------------------------------------------------------------
#define XT (16 * 41)           // floats per x stage
#define WT (16 * 209)          // floats per w stage
__global__ __launch_bounds__(256, 2)
void exact_kernel(const float* __restrict__ x,
                  const float* __restrict__ W,
                  const float* __restrict__ bias) {
    __shared__ float x_s[3 * XT];
    __shared__ float w_s[3 * WT];
    __shared__ int   cind[CPB];

    int tid = threadIdx.x;
    int tx = tid & 15;
    int ty = tid >> 4;                 // 0..15
    int nr   = (ty < 8) ? 3 : 2;       // rows owned (uniform per warp)
    int base = (ty < 8) ? ty * 3 : 24 + (ty - 8) * 2;
    int b  = blockIdx.x >> 2;          // 4 blocks per batch
    int c0 = (blockIdx.x & 3) * CPB;

    if (tid < CPB) cind[tid] = g_cand[b * NCAND + c0 + tid];
    // zero the n>=200 pad region of all 3 w stages (never cp.async'd)
    for (int e = tid; e < 3 * 16 * 9; e += 256) {
        int bf = e / 144, rem = e % 144;
        int kk = rem / 9, n = 200 + rem % 9;
        w_s[bf * WT + kk * 209 + n] = 0.f;
    }
    __syncthreads();

    const float* xb = x + (size_t)b * SS * CC;

    // cp.async fill of chunk c into stage st (4-byte copies, proven layouts)
    auto cpT = [&](int c, int st) {
        int k0 = c * 16;
        // x: 640 elems, 3 rounds
        #pragma unroll
        for (int r = 0; r < 3; r++) {
            int e = tid + r * 256;
            if (e < 640) {
                int m = e >> 4, kk = e & 15;
                uint32_t dst = (uint32_t)__cvta_generic_to_shared(
                    &x_s[st * XT + kk * 41 + m]);
                const float* src = &xb[(size_t)cind[m] * CC + k0 + kk];
                asm volatile("cp.async.ca.shared.global [%0], [%1], 4;"
                             :: "r"(dst), "l"(src));
            }
        }
        // W: 3200 elems (n<200), 13 rounds
        #pragma unroll
        for (int r = 0; r < 13; r++) {
            int e = tid + r * 256;
            if (e < 3200) {
                int n = e >> 4, kk = e & 15;
                uint32_t dst = (uint32_t)__cvta_generic_to_shared(
                    &w_s[st * WT + kk * 209 + n]);
                const float* src = &W[(size_t)n * CC + k0 + kk];
                asm volatile("cp.async.ca.shared.global [%0], [%1], 4;"
                             :: "r"(dst), "l"(src));
            }
        }
    };

    float acc[3][13];
    #pragma unroll
    for (int i = 0; i < 3; i++)
        #pragma unroll
        for (int j = 0; j < 13; j++) acc[i][j] = 0.f;

    cpT(0, 0); asm volatile("cp.async.commit_group;");
    cpT(1, 1); asm volatile("cp.async.commit_group;");

    for (int c = 0; c < NCH16; c++) {
        int st = c % 3;
        asm volatile("cp.async.wait_group 1;");
        __syncthreads();
        if (c + 2 < NCH16) {
            cpT(c + 2, (c + 2) % 3);
            asm volatile("cp.async.commit_group;");
        } else {
            asm volatile("cp.async.commit_group;");   // keep group count in step
        }

        const float* xsb = x_s + st * XT;
        const float* wsb = w_s + st * WT;
        #pragma unroll
        for (int kk = 0; kk < 16; kk++) {
            float xv[3];
            #pragma unroll
            for (int i = 0; i < 3; i++)
                xv[i] = (i < nr) ? xsb[kk * 41 + base + i] : 0.f;
            #pragma unroll
            for (int j = 0; j < 13; j++) {
                float wv = wsb[kk * 209 + tx + 16 * j];
                #pragma unroll
                for (int i = 0; i < 3; i++)
                    if (i < nr) acc[i][j] = fmaf(xv[i], wv, acc[i][j]);
            }
        }
        __syncthreads();
    }

    int id = g_maxid[b];
    #pragma unroll
    for (int i = 0; i < 3; i++) {
        if (i >= nr) break;
        float mx = -1e30f;
        #pragma unroll
        for (int j = 0; j < 13; j++) {
            int n = tx + 16 * j;
            if (n < NN) {
                acc[i][j] += __ldg(&bias[n]);
                mx = fmaxf(mx, acc[i][j]);
            }
        }
        #pragma unroll
        for (int o = 8; o > 0; o >>= 1)
            mx = fmaxf(mx, __shfl_xor_sync(0xffffffffu, mx, o));

        float se = 0.f, lv = 0.f;
        #pragma unroll
        for (int j = 0; j < 13; j++) {
            int n = tx + 16 * j;
            if (n < NN) {
                se += expf(acc[i][j] - mx);
                if (n == id) lv = acc[i][j];
            }
        }
        #pragma unroll
        for (int o = 8; o > 0; o >>= 1) {
            se += __shfl_xor_sync(0xffffffffu, se, o);
            lv += __shfl_xor_sync(0xffffffffu, lv, o);
        }
        if (tx == 0)
            g_cscore[b * NCAND + c0 + base + i] = lv - mx - logf(se);
    }
}

// ---------------------------------------------------------------------------
// K6: per-batch sort of 160 candidates (padded to 256) by EXACT score.
// ---------------------------------------------------------------------------
__global__ void sort2_kernel() {
    __shared__ float s[256];
    __shared__ int   si[256];
    int b = blockIdx.x;
    int t = threadIdx.x;
    if (t < NCAND) {
        s[t]  = g_cscore[b * NCAND + t];
        si[t] = g_cand[b * NCAND + t];
    } else {
        s[t]  = -INFINITY;
        si[t] = 1 << 30;
    }
    __syncthreads();
    for (int k = 2; k <= 256; k <<= 1) {
        for (int j = k >> 1; j > 0; j >>= 1) {
            int ixj = t ^ j;
            if (ixj > t) {
                float a = s[t],  c = s[ixj];
                int  ai = si[t], ci = si[ixj];
                bool aBetter = (a > c) || (a == c && ai < ci);
                bool descHere = ((t & k) == 0);
                bool doSwap = descHere ? !aBetter : aBetter;
                if (doSwap) {
                    s[t] = c;  s[ixj] = a;
                    si[t] = ci; si[ixj] = ai;
                }
            }
            __syncthreads();
        }
    }
    if (t < KSEL) g_topk[b * KSEL + t] = si[t];
}

// ---------------------------------------------------------------------------
// K7: gather out[b, j, :] = x[b, topk[b][j], :]  (float4 vectorized)
// ---------------------------------------------------------------------------
__global__ void gather_kernel(const float* __restrict__ x,
                              float* __restrict__ out) {
    int row = blockIdx.x;
    int b = row >> 7, j = row & (KSEL - 1);
    int sidx = g_topk[b * KSEL + j];
    const float4* src = (const float4*)(x + ((size_t)b * SS + sidx) * CC);
    float4* dst = (float4*)(out + (size_t)row * CC);
    for (int c = threadIdx.x; c < CC / 4; c += blockDim.x) dst[c] = src[c];
}

// ---------------------------------------------------------------------------
extern "C" void kernel_launch(void* const* d_in, const int* in_sizes, int n_in,
                              void* d_out, int out_size) {
    const float* x    = (const float*)d_in[0];   // [32, 2048, 1536]
    const float* W    = (const float*)d_in[1];   // [200, 1536]
    const float* bias = (const float*)d_in[2];   // [200]
    float* out = (float*)d_out;                  // [32, 128, 1536]

    cudaFuncSetAttribute(score_mma_kernel,
                         cudaFuncAttributeMaxDynamicSharedMemorySize, SMEMB);

    wconv_kernel<<<(NCH16 * WCH1 + 255) / 256, 256>>>(W);
    score_mma_kernel<<<TOT / 128, 256, SMEMB>>>(x, bias);
    argmax2_kernel<<<BB, 256>>>();
    cand_kernel<<<BB, 1024>>>();
    exact_kernel<<<BB * (NCAND / CPB), 256>>>(x, W, bias);
    sort2_kernel<<<BB, 256>>>();
    gather_kernel<<<BB * KSEL, 256>>>(x, out);
}

// round 15
// speedup vs baseline: 1.2854x; 1.2854x over previous
#include <cuda_runtime.h>
#include <cuda_bf16.h>
#include <math.h>
#include <stdint.h>

// Problem dims
#define BB 32
#define SS 2048
#define CC 1536
#define NN 200
#define KSEL 128
#define NCAND 160             // candidate pool per batch (32-rank margin)
#define CPB 40                // candidates per exact block (4 blocks/batch)
#define TOT (BB * SS)         // 65536 tokens

#define NPAD 208              // class dim: 7/7/6/6 n-tiles across 4 N-warps
#define NCH16 96              // K chunks of 16
#define NCH32 48              // K chunks of 32
#define WCH1 (NPAD * 8)       // u32 per k16 chunk of swizzled W = 1664

// Scratch (no cudaMalloc allowed)
__device__ float g_logits[(size_t)NN * TOT];   // [n][token], 52.4 MB
__device__ float g_lse[TOT];                   // per-token logsumexp
__device__ float g_msum[BB * NN];              // per-(b,n) logit sums (atomic)
__device__ int   g_maxid[BB];
__device__ int   g_cand[BB * NCAND];           // candidate token indices
__device__ float g_cscore[BB * NCAND];         // exact scores of candidates
__device__ int   g_topk[BB * KSEL];
__device__ __align__(16) uint32_t g_wswz[NCH16 * WCH1];

__device__ __forceinline__ uint32_t pack2bf(float a, float b) {
    __nv_bfloat162 p = __float22bfloat162_rn(make_float2(a, b));
    return *reinterpret_cast<uint32_t*>(&p);
}

// ---------------------------------------------------------------------------
// K-1: W -> bf16, fragment-swizzled in global (proven). Also zeroes g_msum.
// ---------------------------------------------------------------------------
__global__ void wconv_kernel(const float* __restrict__ W) {
    int i = blockIdx.x * blockDim.x + threadIdx.x;
    if (i < BB * NN) g_msum[i] = 0.f;
    if (i >= NCH16 * WCH1) return;
    int c = i / WCH1;
    int rem = i % WCH1;
    int n = rem >> 3, p = rem & 7;
    float v0 = 0.f, v1 = 0.f;
    if (n < NN) {
        int k = c * 16 + 2 * p;
        v0 = W[(size_t)n * CC + k];
        v1 = W[(size_t)n * CC + k + 1];
    }
    int w = (p & 3) * 2 + (p >> 2);
    g_wswz[c * WCH1 + n * 8 + w] = pack2bf(v0, v1);
}

// ---------------------------------------------------------------------------
// K2: APPROX logits GEMM (register MMA, bf16, k32 chunks, cp.async W).
// Round-13 proven structure; ONLY change: NPAD 224->208 (26 n-tiles) with
// SMSP-balanced warp mapping mw=warp&1, nw=warp>>1 (each SMSP gets one
// 7-tile warp + one 6-tile warp -> 104 HMMA/SMSP/chunk, -7%).
// ---------------------------------------------------------------------------
#define MMA_BF16(d, a, b0_, b1_)                                            \
    asm volatile(                                                           \
        "mma.sync.aligned.m16n8k16.row.col.f32.bf16.bf16.f32 "              \
        "{%0,%1,%2,%3}, {%4,%5,%6,%7}, {%8,%9}, {%0,%1,%2,%3};"             \
        : "+f"(d[0]), "+f"(d[1]), "+f"(d[2]), "+f"(d[3])                    \
        : "r"(a[0]), "r"(a[1]), "r"(a[2]), "r"(a[3]), "r"(b0_), "r"(b1_))

#define XSBUF 2048            // u32 per x stage: [2 half][128][8]
#define WSBUF (2 * WCH1)      // u32 per W stage: [2 half][208][8] = 3328
#define SMEMB ((2 * XSBUF + 3 * WSBUF + NPAD + 2 * 512) * 4)

__global__ __launch_bounds__(256, 1)
void score_mma_kernel(const float* __restrict__ x,
                      const float* __restrict__ bias) {
    extern __shared__ uint32_t sm[];
    uint32_t* xs = sm;                        // [2 buf][2 half][128][8]
    uint32_t* ws = sm + 2 * XSBUF;            // [3 buf][2 half][208][8]
    float* bias_s = (float*)(ws + 3 * WSBUF); // [208]
    float* p_mx = bias_s + NPAD;              // [128][4]
    float* p_se = p_mx + 512;

    int tid  = threadIdx.x;
    int warp = tid >> 5, lane = tid & 31;
    int gid  = lane >> 2, tig = lane & 3;
    int mw   = warp & 1;                      // SMSP-balanced mapping
    int nw   = warp >> 1;                     // nw 0..3
    int ntc   = (nw < 2) ? 7 : 6;             // n-tiles this warp
    int nbase = (nw < 2) ? nw * 56 : 112 + (nw - 2) * 48;
    int token0 = blockIdx.x * 128;            // 16 blocks per batch
    int b = token0 >> 11;

    for (int n = tid; n < NPAD; n += 256)
        bias_s[n] = (n < NN) ? __ldg(&bias[n]) : -1e30f;

    float acc[4][7][4];
    #pragma unroll
    for (int mt = 0; mt < 4; mt++)
        #pragma unroll
        for (int nt = 0; nt < 7; nt++)
            #pragma unroll
            for (int r = 0; r < 4; r++) acc[mt][nt][r] = 0.f;

    const float* xbase = x + (size_t)token0 * CC;

    int xrow = tid >> 3;            // 0..31; tasks at rows +0,+32,+64,+96
    int xp   = tid & 7;
    int xw   = (xp & 3) * 2 + (xp >> 2);
    float2 rx[4][2];                // [task][half]

    auto ldx = [&](int c) {
        #pragma unroll
        for (int t = 0; t < 4; t++) {
            const float* p = xbase + (size_t)(xrow + 32 * t) * CC + c * 32 + 2 * xp;
            rx[t][0] = *(const float2*)p;
            rx[t][1] = *(const float2*)(p + 16);
        }
    };
    auto stx = [&](int xb) {
        uint32_t* base = xs + xb * XSBUF;
        #pragma unroll
        for (int t = 0; t < 4; t++) {
            int r = xrow + 32 * t;
            base[0 * 1024 + r * 8 + xw] = pack2bf(rx[t][0].x, rx[t][0].y);
            base[1 * 1024 + r * 8 + xw] = pack2bf(rx[t][1].x, rx[t][1].y);
        }
    };
    auto cpW = [&](int c, int wb) {
        const uint4* src = (const uint4*)(g_wswz + (size_t)(2 * c) * WCH1);
        uint32_t dst = (uint32_t)__cvta_generic_to_shared(ws + wb * WSBUF);
        #pragma unroll
        for (int r = 0; r < 3; r++) {
            int e = tid + r * 256;
            asm volatile("cp.async.cg.shared.global [%0], [%1], 16;"
                         :: "r"(dst + e * 16), "l"(src + e));
        }
        if (tid < 64) {
            int e = tid + 768;                 // 832 uint4 total (3328 u32)
            asm volatile("cp.async.cg.shared.global [%0], [%1], 16;"
                         :: "r"(dst + e * 16), "l"(src + e));
        }
    };

    cpW(0, 0); asm volatile("cp.async.commit_group;");
    cpW(1, 1); asm volatile("cp.async.commit_group;");
    ldx(0); stx(0);
    ldx(1);
    asm volatile("cp.async.wait_group 1;");
    __syncthreads();

    for (int c = 0; c < NCH32; c++) {
        int xb = c & 1, wb = c % 3;
        const uint32_t* xsb = xs + xb * XSBUF;
        const uint32_t* wsb = ws + wb * WSBUF;

        #pragma unroll
        for (int h = 0; h < 2; h++) {
            uint32_t af[4][4];
            #pragma unroll
            for (int mt = 0; mt < 4; mt++) {
                int row0 = mw * 64 + mt * 16 + gid;
                const uint32_t* pa = xsb + h * 1024 + row0 * 8 + tig * 2;
                uint2 t0 = *(const uint2*)pa;
                uint2 t1 = *(const uint2*)(pa + 64);
                af[mt][0] = t0.x;  af[mt][2] = t0.y;
                af[mt][1] = t1.x;  af[mt][3] = t1.y;
            }
            #pragma unroll
            for (int nt = 0; nt < 7; nt++) {
                if (nt >= ntc) break;
                int nrow = nbase + nt * 8 + gid;
                uint2 B0 = *(const uint2*)(wsb + h * WCH1 + nrow * 8 + tig * 2);
                MMA_BF16(acc[0][nt], af[0], B0.x, B0.y);
                MMA_BF16(acc[1][nt], af[1], B0.x, B0.y);
                MMA_BF16(acc[2][nt], af[2], B0.x, B0.y);
                MMA_BF16(acc[3][nt], af[3], B0.x, B0.y);
            }
        }

        if (c + 1 < NCH32) {
            stx(xb ^ 1);
            if (c + 2 < NCH32) { ldx(c + 2); cpW(c + 2, (c + 2) % 3); }
            asm volatile("cp.async.commit_group;");
            asm volatile("cp.async.wait_group 1;");
            __syncthreads();
        }
    }

    // ---- bias add + logit store (transposed [n][token]) + fused class sums
    #pragma unroll
    for (int nt = 0; nt < 7; nt++) {
        if (nt >= ntc) break;
        int n0 = nbase + nt * 8 + tig * 2;
        float b0 = bias_s[n0], b1 = bias_s[n0 + 1];
        #pragma unroll
        for (int mt = 0; mt < 4; mt++) {
            acc[mt][nt][0] += b0; acc[mt][nt][1] += b1;
            acc[mt][nt][2] += b0; acc[mt][nt][3] += b1;
        }
        if (n0 < NN) {
            #pragma unroll
            for (int mt = 0; mt < 4; mt++) {
                int r0 = token0 + mw * 64 + mt * 16 + gid;
                g_logits[(size_t)n0 * TOT + r0]           = acc[mt][nt][0];
                g_logits[(size_t)(n0 + 1) * TOT + r0]     = acc[mt][nt][1];
                g_logits[(size_t)n0 * TOT + r0 + 8]       = acc[mt][nt][2];
                g_logits[(size_t)(n0 + 1) * TOT + r0 + 8] = acc[mt][nt][3];
            }
        }

        float s0 = 0.f, s1 = 0.f;
        #pragma unroll
        for (int mt = 0; mt < 4; mt++) {
            s0 += acc[mt][nt][0] + acc[mt][nt][2];
            s1 += acc[mt][nt][1] + acc[mt][nt][3];
        }
        #pragma unroll
        for (int o = 4; o <= 16; o <<= 1) {
            s0 += __shfl_xor_sync(0xffffffffu, s0, o);
            s1 += __shfl_xor_sync(0xffffffffu, s1, o);
        }
        if (gid == 0 && n0 < NN) {
            atomicAdd(&g_msum[b * NN + n0], s0);
            if (n0 + 1 < NN) atomicAdd(&g_msum[b * NN + n0 + 1], s1);
        }
    }

    #pragma unroll
    for (int mt = 0; mt < 4; mt++) {
        #pragma unroll
        for (int half = 0; half < 2; half++) {
            float mx = -1e30f;
            #pragma unroll
            for (int nt = 0; nt < 7; nt++) {
                if (nt >= ntc) break;
                mx = fmaxf(mx, fmaxf(acc[mt][nt][2 * half],
                                     acc[mt][nt][2 * half + 1]));
            }
            mx = fmaxf(mx, __shfl_xor_sync(0xffffffffu, mx, 1));
            mx = fmaxf(mx, __shfl_xor_sync(0xffffffffu, mx, 2));

            float se = 0.f;
            #pragma unroll
            for (int nt = 0; nt < 7; nt++) {
                if (nt >= ntc) break;
                se += expf(acc[mt][nt][2 * half] - mx)
                    + expf(acc[mt][nt][2 * half + 1] - mx);
            }
            se += __shfl_xor_sync(0xffffffffu, se, 1);
            se += __shfl_xor_sync(0xffffffffu, se, 2);

            if (tig == 0) {
                int row = mw * 64 + mt * 16 + half * 8 + gid;
                p_mx[row * 4 + nw] = mx;
                p_se[row * 4 + nw] = se;
            }
        }
    }
    __syncthreads();

    if (tid < 128) {
        float m0 = p_mx[tid * 4 + 0], m1 = p_mx[tid * 4 + 1];
        float m2 = p_mx[tid * 4 + 2], m3 = p_mx[tid * 4 + 3];
        float M = fmaxf(fmaxf(m0, m1), fmaxf(m2, m3));
        float se = p_se[tid * 4 + 0] * expf(m0 - M)
                 + p_se[tid * 4 + 1] * expf(m1 - M)
                 + p_se[tid * 4 + 2] * expf(m2 - M)
                 + p_se[tid * 4 + 3] * expf(m3 - M);
        g_lse[token0 + tid] = M + logf(se);
    }
}

// ---------------------------------------------------------------------------
// K3: per-batch argmax over the NN class sums.
// ---------------------------------------------------------------------------
__global__ void argmax2_kernel() {
    __shared__ float vals[256];
    __shared__ int   idxs[256];
    int b = blockIdx.x, n = threadIdx.x;
    vals[n] = (n < NN) ? g_msum[b * NN + n] : -INFINITY;
    idxs[n] = (n < NN) ? n : (1 << 30);
    __syncthreads();
    for (int o = 128; o > 0; o >>= 1) {
        if (n < o) {
            float v2 = vals[n + o]; int i2 = idxs[n + o];
            float v1 = vals[n];     int i1 = idxs[n];
            if (v2 > v1 || (v2 == v1 && i2 < i1)) { vals[n] = v2; idxs[n] = i2; }
        }
        __syncthreads();
    }
    if (n == 0) g_maxid[b] = idxs[0];
}

// ---------------------------------------------------------------------------
// K4: per-batch bitonic sort of 2048 approx scores -> top-160 candidates.
// ---------------------------------------------------------------------------
__global__ void cand_kernel() {
    __shared__ float s[SS];
    __shared__ int   si[SS];
    int b = blockIdx.x;
    int id = g_maxid[b];
    const float* lg = g_logits + (size_t)id * TOT + b * SS;
    const float* ls = g_lse + b * SS;
    for (int t = threadIdx.x; t < SS; t += blockDim.x) {
        s[t]  = lg[t] - ls[t];
        si[t] = t;
    }
    __syncthreads();
    for (int k = 2; k <= SS; k <<= 1) {
        for (int j = k >> 1; j > 0; j >>= 1) {
            for (int t = threadIdx.x; t < SS; t += blockDim.x) {
                int ixj = t ^ j;
                if (ixj > t) {
                    float a = s[t],  c = s[ixj];
                    int  ai = si[t], ci = si[ixj];
                    bool aBetter = (a > c) || (a == c && ai < ci);
                    bool descHere = ((t & k) == 0);
                    bool doSwap = descHere ? !aBetter : aBetter;
                    if (doSwap) {
                        s[t] = c;  s[ixj] = a;
                        si[t] = ci; si[ixj] = ai;
                    }
                }
            }
            __syncthreads();
        }
    }
    for (int t = threadIdx.x; t < NCAND; t += blockDim.x)
        g_cand[b * NCAND + t] = si[t];
}

// ---------------------------------------------------------------------------
// K5: EXACT rescore — VERBATIM round-13 version (proven 508.5us). 40 cand/
// block, 256 threads, uneven-balanced rows (warps 0-3: 3 rows, 4-7: 2 rows).
// ---------------------------------------------------------------------------
__global__ __launch_bounds__(256, 2)
void exact_kernel(const float* __restrict__ x,
                  const float* __restrict__ W,
                  const float* __restrict__ bias) {
    __shared__ float x_s[16 * 41];    // [kk][m], m<40, stride 41
    __shared__ float w_s[16 * 209];
    __shared__ int   cind[CPB];

    int tid = threadIdx.x;
    int tx = tid & 15;
    int ty = tid >> 4;                 // 0..15
    int nr   = (ty < 8) ? 3 : 2;       // rows owned (uniform per warp)
    int base = (ty < 8) ? ty * 3 : 24 + (ty - 8) * 2;
    int b  = blockIdx.x >> 2;          // 4 blocks per batch
    int c0 = (blockIdx.x & 3) * CPB;

    if (tid < CPB) cind[tid] = g_cand[b * NCAND + c0 + tid];
    __syncthreads();

    float acc[3][13];
    #pragma unroll
    for (int i = 0; i < 3; i++)
        #pragma unroll
        for (int j = 0; j < 13; j++) acc[i][j] = 0.f;

    const float* xb = x + (size_t)b * SS * CC;

    for (int k0 = 0; k0 < CC; k0 += 16) {
        // x tile: 40 x 16 = 640 elems
        #pragma unroll
        for (int r = 0; r < 3; r++) {
            int e = tid + r * 256;
            if (e < 640) {
                int m = e >> 4, kk = e & 15;
                x_s[kk * 41 + m] = xb[(size_t)cind[m] * CC + k0 + kk];
            }
        }
        #pragma unroll
        for (int r = 0; r < 13; r++) {
            int e = tid + r * 256;
            if (e < 3328) {
                int n = e >> 4, kk = e & 15;
                w_s[kk * 209 + n] =
                    (n < NN) ? __ldg(&W[(size_t)n * CC + k0 + kk]) : 0.f;
            }
        }
        __syncthreads();

        #pragma unroll
        for (int kk = 0; kk < 16; kk++) {
            float xv[3];
            #pragma unroll
            for (int i = 0; i < 3; i++)
                xv[i] = (i < nr) ? x_s[kk * 41 + base + i] : 0.f;
            #pragma unroll
            for (int j = 0; j < 13; j++) {
                float wv = w_s[kk * 209 + tx + 16 * j];
                #pragma unroll
                for (int i = 0; i < 3; i++)
                    if (i < nr) acc[i][j] = fmaf(xv[i], wv, acc[i][j]);
            }
        }
        __syncthreads();
    }

    int id = g_maxid[b];
    #pragma unroll
    for (int i = 0; i < 3; i++) {
        if (i >= nr) break;
        float mx = -1e30f;
        #pragma unroll
        for (int j = 0; j < 13; j++) {
            int n = tx + 16 * j;
            if (n < NN) {
                acc[i][j] += __ldg(&bias[n]);
                mx = fmaxf(mx, acc[i][j]);
            }
        }
        #pragma unroll
        for (int o = 8; o > 0; o >>= 1)
            mx = fmaxf(mx, __shfl_xor_sync(0xffffffffu, mx, o));

        float se = 0.f, lv = 0.f;
        #pragma unroll
        for (int j = 0; j < 13; j++) {
            int n = tx + 16 * j;
            if (n < NN) {
                se += expf(acc[i][j] - mx);
                if (n == id) lv = acc[i][j];
            }
        }
        #pragma unroll
        for (int o = 8; o > 0; o >>= 1) {
            se += __shfl_xor_sync(0xffffffffu, se, o);
            lv += __shfl_xor_sync(0xffffffffu, lv, o);
        }
        if (tx == 0)
            g_cscore[b * NCAND + c0 + base + i] = lv - mx - logf(se);
    }
}

// ---------------------------------------------------------------------------
// K6: per-batch sort of 160 candidates (padded to 256) by EXACT score.
// ---------------------------------------------------------------------------
__global__ void sort2_kernel() {
    __shared__ float s[256];
    __shared__ int   si[256];
    int b = blockIdx.x;
    int t = threadIdx.x;
    if (t < NCAND) {
        s[t]  = g_cscore[b * NCAND + t];
        si[t] = g_cand[b * NCAND + t];
    } else {
        s[t]  = -INFINITY;
        si[t] = 1 << 30;
    }
    __syncthreads();
    for (int k = 2; k <= 256; k <<= 1) {
        for (int j = k >> 1; j > 0; j >>= 1) {
            int ixj = t ^ j;
            if (ixj > t) {
                float a = s[t],  c = s[ixj];
                int  ai = si[t], ci = si[ixj];
                bool aBetter = (a > c) || (a == c && ai < ci);
                bool descHere = ((t & k) == 0);
                bool doSwap = descHere ? !aBetter : aBetter;
                if (doSwap) {
                    s[t] = c;  s[ixj] = a;
                    si[t] = ci; si[ixj] = ai;
                }
            }
            __syncthreads();
        }
    }
    if (t < KSEL) g_topk[b * KSEL + t] = si[t];
}

// ---------------------------------------------------------------------------
// K7: gather out[b, j, :] = x[b, topk[b][j], :]  (float4 vectorized)
// ---------------------------------------------------------------------------
__global__ void gather_kernel(const float* __restrict__ x,
                              float* __restrict__ out) {
    int row = blockIdx.x;
    int b = row >> 7, j = row & (KSEL - 1);
    int sidx = g_topk[b * KSEL + j];
    const float4* src = (const float4*)(x + ((size_t)b * SS + sidx) * CC);
    float4* dst = (float4*)(out + (size_t)row * CC);
    for (int c = threadIdx.x; c < CC / 4; c += blockDim.x) dst[c] = src[c];
}

// ---------------------------------------------------------------------------
extern "C" void kernel_launch(void* const* d_in, const int* in_sizes, int n_in,
                              void* d_out, int out_size) {
    const float* x    = (const float*)d_in[0];   // [32, 2048, 1536]
    const float* W    = (const float*)d_in[1];   // [200, 1536]
    const float* bias = (const float*)d_in[2];   // [200]
    float* out = (float*)d_out;                  // [32, 128, 1536]

    cudaFuncSetAttribute(score_mma_kernel,
                         cudaFuncAttributeMaxDynamicSharedMemorySize, SMEMB);

    wconv_kernel<<<(NCH16 * WCH1 + 255) / 256, 256>>>(W);
    score_mma_kernel<<<TOT / 128, 256, SMEMB>>>(x, bias);
    argmax2_kernel<<<BB, 256>>>();
    cand_kernel<<<BB, 1024>>>();
    exact_kernel<<<BB * (NCAND / CPB), 256>>>(x, W, bias);
    sort2_kernel<<<BB, 256>>>();
    gather_kernel<<<BB * KSEL, 256>>>(x, out);
}

// round 16
// speedup vs baseline: 1.3029x; 1.0136x over previous
#include <cuda_runtime.h>
#include <cuda_bf16.h>
#include <math.h>
#include <stdint.h>

// Problem dims
#define BB 32
#define SS 2048
#define CC 1536
#define NN 200
#define KSEL 128
#define NCAND 160             // candidate pool per batch (32-rank margin)
#define CPB 40                // candidates per exact block (4 blocks/batch)
#define TOT (BB * SS)         // 65536 tokens

#define NPAD 208              // class dim: 7/7/6/6 n-tiles across 4 N-warps
#define NCH16 96              // K chunks of 16
#define NCH64 24              // K chunks of 64
#define WCH1 (NPAD * 8)       // u32 per k16 chunk of swizzled W = 1664

// Scratch (no cudaMalloc allowed)
__device__ float g_logits[(size_t)NN * TOT];   // [n][token], 52.4 MB
__device__ float g_lse[TOT];                   // per-token logsumexp
__device__ float g_msum[BB * NN];              // per-(b,n) logit sums (atomic)
__device__ int   g_maxid[BB];
__device__ int   g_cand[BB * NCAND];           // candidate token indices
__device__ float g_cscore[BB * NCAND];         // exact scores of candidates
__device__ int   g_topk[BB * KSEL];
__device__ __align__(16) uint32_t g_wswz[NCH16 * WCH1];

__device__ __forceinline__ uint32_t pack2bf(float a, float b) {
    __nv_bfloat162 p = __float22bfloat162_rn(make_float2(a, b));
    return *reinterpret_cast<uint32_t*>(&p);
}

// ---------------------------------------------------------------------------
// K-1: W -> bf16, fragment-swizzled in global (proven). Also zeroes g_msum.
// ---------------------------------------------------------------------------
__global__ void wconv_kernel(const float* __restrict__ W) {
    int i = blockIdx.x * blockDim.x + threadIdx.x;
    if (i < BB * NN) g_msum[i] = 0.f;
    if (i >= NCH16 * WCH1) return;
    int c = i / WCH1;
    int rem = i % WCH1;
    int n = rem >> 3, p = rem & 7;
    float v0 = 0.f, v1 = 0.f;
    if (n < NN) {
        int k = c * 16 + 2 * p;
        v0 = W[(size_t)n * CC + k];
        v1 = W[(size_t)n * CC + k + 1];
    }
    int w = (p & 3) * 2 + (p >> 2);
    g_wswz[c * WCH1 + n * 8 + w] = pack2bf(v0, v1);
}

// ---------------------------------------------------------------------------
// K2: APPROX logits GEMM (register MMA, bf16). v5: k64 chunks (24 iters,
// half the barriers of the proven k32 version). Per-k16-half fragment
// addressing and all arithmetic identical to the proven r13/r15 kernel.
// x staged in two k32 sub-steps between MMA sub-phases (rx stays 16 regs).
// 8 warps = 2(M) x 4(N) via SMSP-balanced mapping; NPAD 208; fused csum.
// ---------------------------------------------------------------------------
#define MMA_BF16(d, a, b0_, b1_)                                            \
    asm volatile(                                                           \
        "mma.sync.aligned.m16n8k16.row.col.f32.bf16.bf16.f32 "              \
        "{%0,%1,%2,%3}, {%4,%5,%6,%7}, {%8,%9}, {%0,%1,%2,%3};"             \
        : "+f"(d[0]), "+f"(d[1]), "+f"(d[2]), "+f"(d[3])                    \
        : "r"(a[0]), "r"(a[1]), "r"(a[2]), "r"(a[3]), "r"(b0_), "r"(b1_))

#define XS64 4096             // u32 per x stage: [4 half][128][8]
#define WS64 (4 * WCH1)       // u32 per W stage: [4 k16][208][8] = 6656
#define SMEMB ((2 * XS64 + 2 * WS64 + NPAD + 2 * 512) * 4)

__global__ __launch_bounds__(256, 1)
void score_mma_kernel(const float* __restrict__ x,
                      const float* __restrict__ bias) {
    extern __shared__ uint32_t sm[];
    uint32_t* xs = sm;                        // [2 buf][4 half][128][8]
    uint32_t* ws = sm + 2 * XS64;             // [2 buf][4 k16][208][8]
    float* bias_s = (float*)(ws + 2 * WS64);  // [208]
    float* p_mx = bias_s + NPAD;              // [128][4]
    float* p_se = p_mx + 512;

    int tid  = threadIdx.x;
    int warp = tid >> 5, lane = tid & 31;
    int gid  = lane >> 2, tig = lane & 3;
    int mw   = warp & 1;                      // SMSP-balanced mapping
    int nw   = warp >> 1;                     // nw 0..3
    int ntc   = (nw < 2) ? 7 : 6;             // n-tiles this warp
    int nbase = (nw < 2) ? nw * 56 : 112 + (nw - 2) * 48;
    int token0 = blockIdx.x * 128;            // 16 blocks per batch
    int b = token0 >> 11;

    for (int n = tid; n < NPAD; n += 256)
        bias_s[n] = (n < NN) ? __ldg(&bias[n]) : -1e30f;

    float acc[4][7][4];
    #pragma unroll
    for (int mt = 0; mt < 4; mt++)
        #pragma unroll
        for (int nt = 0; nt < 7; nt++)
            #pragma unroll
            for (int r = 0; r < 4; r++) acc[mt][nt][r] = 0.f;

    const float* xbase = x + (size_t)token0 * CC;

    int xrow = tid >> 3;            // 0..31; tasks at rows +0,+32,+64,+96
    int xp   = tid & 7;
    int xw   = (xp & 3) * 2 + (xp >> 2);
    float2 rx[4][2];                // [task][k16-half within sub]

    // load k32 sub s (0/1) of k64 chunk c into registers
    auto ldxs = [&](int c, int s) {
        #pragma unroll
        for (int t = 0; t < 4; t++) {
            const float* p = xbase + (size_t)(xrow + 32 * t) * CC
                           + c * 64 + s * 32 + 2 * xp;
            rx[t][0] = *(const float2*)p;
            rx[t][1] = *(const float2*)(p + 16);
        }
    };
    // store rx into buffer buf, sub s (global halves 2s, 2s+1)
    auto stxs = [&](int buf, int s) {
        uint32_t* base = xs + buf * XS64 + s * 2048;
        #pragma unroll
        for (int t = 0; t < 4; t++) {
            int r = xrow + 32 * t;
            base[0 * 1024 + r * 8 + xw] = pack2bf(rx[t][0].x, rx[t][0].y);
            base[1 * 1024 + r * 8 + xw] = pack2bf(rx[t][1].x, rx[t][1].y);
        }
    };
    // cp.async W for k64 chunk c into buffer wb: 6656 u32 = 1664 uint4
    auto cpW = [&](int c, int wb) {
        const uint4* src = (const uint4*)(g_wswz + (size_t)(4 * c) * WCH1);
        uint32_t dst = (uint32_t)__cvta_generic_to_shared(ws + wb * WS64);
        #pragma unroll
        for (int r = 0; r < 6; r++) {
            int e = tid + r * 256;
            asm volatile("cp.async.cg.shared.global [%0], [%1], 16;"
                         :: "r"(dst + e * 16), "l"(src + e));
        }
        if (tid < 128) {
            int e = tid + 1536;                // 1664 total
            asm volatile("cp.async.cg.shared.global [%0], [%1], 16;"
                         :: "r"(dst + e * 16), "l"(src + e));
        }
    };

    // MMA over one k16 half h of buffer buf (identical math to proven kernel)
    auto mma_half = [&](const uint32_t* xsb, const uint32_t* wsb, int h) {
        uint32_t af[4][4];
        #pragma unroll
        for (int mt = 0; mt < 4; mt++) {
            int row0 = mw * 64 + mt * 16 + gid;
            const uint32_t* pa = xsb + h * 1024 + row0 * 8 + tig * 2;
            uint2 t0 = *(const uint2*)pa;
            uint2 t1 = *(const uint2*)(pa + 64);
            af[mt][0] = t0.x;  af[mt][2] = t0.y;
            af[mt][1] = t1.x;  af[mt][3] = t1.y;
        }
        #pragma unroll
        for (int nt = 0; nt < 7; nt++) {
            if (nt >= ntc) break;
            int nrow = nbase + nt * 8 + gid;
            uint2 B0 = *(const uint2*)(wsb + h * WCH1 + nrow * 8 + tig * 2);
            MMA_BF16(acc[0][nt], af[0], B0.x, B0.y);
            MMA_BF16(acc[1][nt], af[1], B0.x, B0.y);
            MMA_BF16(acc[2][nt], af[2], B0.x, B0.y);
            MMA_BF16(acc[3][nt], af[3], B0.x, B0.y);
        }
    };

    // Prologue: W0 in flight; x chunk 0 fully staged in buf0; rx <- (1, sub0)
    cpW(0, 0); asm volatile("cp.async.commit_group;");
    ldxs(0, 0); stxs(0, 0);
    ldxs(0, 1); stxs(0, 1);
    ldxs(1, 0);
    asm volatile("cp.async.wait_group 0;");
    __syncthreads();

    for (int c = 0; c < NCH64; c++) {
        int buf = c & 1;
        const uint32_t* xsb = xs + buf * XS64;
        const uint32_t* wsb = ws + buf * WS64;

        if (c + 1 < NCH64) { cpW(c + 1, buf ^ 1);
                             asm volatile("cp.async.commit_group;"); }

        mma_half(xsb, wsb, 0);
        mma_half(xsb, wsb, 1);
        if (c + 1 < NCH64) { stxs(buf ^ 1, 0); ldxs(c + 1, 1); }
        mma_half(xsb, wsb, 2);
        mma_half(xsb, wsb, 3);
        if (c + 1 < NCH64) {
            stxs(buf ^ 1, 1);
            if (c + 2 < NCH64) ldxs(c + 2, 0);
            asm volatile("cp.async.wait_group 0;");
            __syncthreads();
        }
    }

    // ---- bias add + logit store (transposed [n][token]) + fused class sums
    #pragma unroll
    for (int nt = 0; nt < 7; nt++) {
        if (nt >= ntc) break;
        int n0 = nbase + nt * 8 + tig * 2;
        float b0 = bias_s[n0], b1 = bias_s[n0 + 1];
        #pragma unroll
        for (int mt = 0; mt < 4; mt++) {
            acc[mt][nt][0] += b0; acc[mt][nt][1] += b1;
            acc[mt][nt][2] += b0; acc[mt][nt][3] += b1;
        }
        if (n0 < NN) {
            #pragma unroll
            for (int mt = 0; mt < 4; mt++) {
                int r0 = token0 + mw * 64 + mt * 16 + gid;
                g_logits[(size_t)n0 * TOT + r0]           = acc[mt][nt][0];
                g_logits[(size_t)(n0 + 1) * TOT + r0]     = acc[mt][nt][1];
                g_logits[(size_t)n0 * TOT + r0 + 8]       = acc[mt][nt][2];
                g_logits[(size_t)(n0 + 1) * TOT + r0 + 8] = acc[mt][nt][3];
            }
        }

        float s0 = 0.f, s1 = 0.f;
        #pragma unroll
        for (int mt = 0; mt < 4; mt++) {
            s0 += acc[mt][nt][0] + acc[mt][nt][2];
            s1 += acc[mt][nt][1] + acc[mt][nt][3];
        }
        #pragma unroll
        for (int o = 4; o <= 16; o <<= 1) {
            s0 += __shfl_xor_sync(0xffffffffu, s0, o);
            s1 += __shfl_xor_sync(0xffffffffu, s1, o);
        }
        if (gid == 0 && n0 < NN) {
            atomicAdd(&g_msum[b * NN + n0], s0);
            if (n0 + 1 < NN) atomicAdd(&g_msum[b * NN + n0 + 1], s1);
        }
    }

    #pragma unroll
    for (int mt = 0; mt < 4; mt++) {
        #pragma unroll
        for (int half = 0; half < 2; half++) {
            float mx = -1e30f;
            #pragma unroll
            for (int nt = 0; nt < 7; nt++) {
                if (nt >= ntc) break;
                mx = fmaxf(mx, fmaxf(acc[mt][nt][2 * half],
                                     acc[mt][nt][2 * half + 1]));
            }
            mx = fmaxf(mx, __shfl_xor_sync(0xffffffffu, mx, 1));
            mx = fmaxf(mx, __shfl_xor_sync(0xffffffffu, mx, 2));

            float se = 0.f;
            #pragma unroll
            for (int nt = 0; nt < 7; nt++) {
                if (nt >= ntc) break;
                se += expf(acc[mt][nt][2 * half] - mx)
                    + expf(acc[mt][nt][2 * half + 1] - mx);
            }
            se += __shfl_xor_sync(0xffffffffu, se, 1);
            se += __shfl_xor_sync(0xffffffffu, se, 2);

            if (tig == 0) {
                int row = mw * 64 + mt * 16 + half * 8 + gid;
                p_mx[row * 4 + nw] = mx;
                p_se[row * 4 + nw] = se;
            }
        }
    }
    __syncthreads();

    if (tid < 128) {
        float m0 = p_mx[tid * 4 + 0], m1 = p_mx[tid * 4 + 1];
        float m2 = p_mx[tid * 4 + 2], m3 = p_mx[tid * 4 + 3];
        float M = fmaxf(fmaxf(m0, m1), fmaxf(m2, m3));
        float se = p_se[tid * 4 + 0] * expf(m0 - M)
                 + p_se[tid * 4 + 1] * expf(m1 - M)
                 + p_se[tid * 4 + 2] * expf(m2 - M)
                 + p_se[tid * 4 + 3] * expf(m3 - M);
        g_lse[token0 + tid] = M + logf(se);
    }
}

// ---------------------------------------------------------------------------
// K3: cand_kernel with FUSED per-batch argmax (replaces argmax2 launch).
// Then bitonic sort of 2048 approx scores -> top-160 candidates.
// ---------------------------------------------------------------------------
__global__ void cand_kernel() {
    __shared__ float s[SS];
    __shared__ int   si[SS];
    __shared__ float av[256];
    __shared__ int   ai[256];
    __shared__ int   id_s;
    int b = blockIdx.x;
    int t = threadIdx.x;

    // fused argmax over g_msum[b][0..NN)
    if (t < 256) {
        av[t] = (t < NN) ? g_msum[b * NN + t] : -INFINITY;
        ai[t] = (t < NN) ? t : (1 << 30);
    }
    __syncthreads();
    for (int o = 128; o > 0; o >>= 1) {
        if (t < o) {
            float v2 = av[t + o]; int i2 = ai[t + o];
            float v1 = av[t];     int i1 = ai[t];
            if (v2 > v1 || (v2 == v1 && i2 < i1)) { av[t] = v2; ai[t] = i2; }
        }
        __syncthreads();
    }
    if (t == 0) { id_s = ai[0]; g_maxid[b] = ai[0]; }
    __syncthreads();
    int id = id_s;

    const float* lg = g_logits + (size_t)id * TOT + b * SS;
    const float* ls = g_lse + b * SS;
    for (int e = t; e < SS; e += blockDim.x) {
        s[e]  = lg[e] - ls[e];
        si[e] = e;
    }
    __syncthreads();
    for (int k = 2; k <= SS; k <<= 1) {
        for (int j = k >> 1; j > 0; j >>= 1) {
            for (int e = t; e < SS; e += blockDim.x) {
                int ixj = e ^ j;
                if (ixj > e) {
                    float a = s[e],  c = s[ixj];
                    int  a2 = si[e], c2 = si[ixj];
                    bool aBetter = (a > c) || (a == c && a2 < c2);
                    bool descHere = ((e & k) == 0);
                    bool doSwap = descHere ? !aBetter : aBetter;
                    if (doSwap) {
                        s[e] = c;  s[ixj] = a;
                        si[e] = c2; si[ixj] = a2;
                    }
                }
            }
            __syncthreads();
        }
    }
    for (int e = t; e < NCAND; e += blockDim.x)
        g_cand[b * NCAND + e] = si[e];
}

// ---------------------------------------------------------------------------
// K5: EXACT rescore — VERBATIM round-13 version (proven 508.5us). 40 cand/
// block, 256 threads, uneven-balanced rows (warps 0-3: 3 rows, 4-7: 2 rows).
// ---------------------------------------------------------------------------
__global__ __launch_bounds__(256, 2)
void exact_kernel(const float* __restrict__ x,
                  const float* __restrict__ W,
                  const float* __restrict__ bias) {
    __shared__ float x_s[16 * 41];    // [kk][m], m<40, stride 41
    __shared__ float w_s[16 * 209];
    __shared__ int   cind[CPB];

    int tid = threadIdx.x;
    int tx = tid & 15;
    int ty = tid >> 4;                 // 0..15
    int nr   = (ty < 8) ? 3 : 2;       // rows owned (uniform per warp)
    int base = (ty < 8) ? ty * 3 : 24 + (ty - 8) * 2;
    int b  = blockIdx.x >> 2;          // 4 blocks per batch
    int c0 = (blockIdx.x & 3) * CPB;

    if (tid < CPB) cind[tid] = g_cand[b * NCAND + c0 + tid];
    __syncthreads();

    float acc[3][13];
    #pragma unroll
    for (int i = 0; i < 3; i++)
        #pragma unroll
        for (int j = 0; j < 13; j++) acc[i][j] = 0.f;

    const float* xb = x + (size_t)b * SS * CC;

    for (int k0 = 0; k0 < CC; k0 += 16) {
        // x tile: 40 x 16 = 640 elems
        #pragma unroll
        for (int r = 0; r < 3; r++) {
            int e = tid + r * 256;
            if (e < 640) {
                int m = e >> 4, kk = e & 15;
                x_s[kk * 41 + m] = xb[(size_t)cind[m] * CC + k0 + kk];
            }
        }
        #pragma unroll
        for (int r = 0; r < 13; r++) {
            int e = tid + r * 256;
            if (e < 3328) {
                int n = e >> 4, kk = e & 15;
                w_s[kk * 209 + n] =
                    (n < NN) ? __ldg(&W[(size_t)n * CC + k0 + kk]) : 0.f;
            }
        }
        __syncthreads();

        #pragma unroll
        for (int kk = 0; kk < 16; kk++) {
            float xv[3];
            #pragma unroll
            for (int i = 0; i < 3; i++)
                xv[i] = (i < nr) ? x_s[kk * 41 + base + i] : 0.f;
            #pragma unroll
            for (int j = 0; j < 13; j++) {
                float wv = w_s[kk * 209 + tx + 16 * j];
                #pragma unroll
                for (int i = 0; i < 3; i++)
                    if (i < nr) acc[i][j] = fmaf(xv[i], wv, acc[i][j]);
            }
        }
        __syncthreads();
    }

    int id = g_maxid[b];
    #pragma unroll
    for (int i = 0; i < 3; i++) {
        if (i >= nr) break;
        float mx = -1e30f;
        #pragma unroll
        for (int j = 0; j < 13; j++) {
            int n = tx + 16 * j;
            if (n < NN) {
                acc[i][j] += __ldg(&bias[n]);
                mx = fmaxf(mx, acc[i][j]);
            }
        }
        #pragma unroll
        for (int o = 8; o > 0; o >>= 1)
            mx = fmaxf(mx, __shfl_xor_sync(0xffffffffu, mx, o));

        float se = 0.f, lv = 0.f;
        #pragma unroll
        for (int j = 0; j < 13; j++) {
            int n = tx + 16 * j;
            if (n < NN) {
                se += expf(acc[i][j] - mx);
                if (n == id) lv = acc[i][j];
            }
        }
        #pragma unroll
        for (int o = 8; o > 0; o >>= 1) {
            se += __shfl_xor_sync(0xffffffffu, se, o);
            lv += __shfl_xor_sync(0xffffffffu, lv, o);
        }
        if (tx == 0)
            g_cscore[b * NCAND + c0 + base + i] = lv - mx - logf(se);
    }
}

// ---------------------------------------------------------------------------
// K6: per-batch sort of 160 candidates (padded to 256) by EXACT score.
// ---------------------------------------------------------------------------
__global__ void sort2_kernel() {
    __shared__ float s[256];
    __shared__ int   si[256];
    int b = blockIdx.x;
    int t = threadIdx.x;
    if (t < NCAND) {
        s[t]  = g_cscore[b * NCAND + t];
        si[t] = g_cand[b * NCAND + t];
    } else {
        s[t]  = -INFINITY;
        si[t] = 1 << 30;
    }
    __syncthreads();
    for (int k = 2; k <= 256; k <<= 1) {
        for (int j = k >> 1; j > 0; j >>= 1) {
            int ixj = t ^ j;
            if (ixj > t) {
                float a = s[t],  c = s[ixj];
                int  ai = si[t], ci = si[ixj];
                bool aBetter = (a > c) || (a == c && ai < ci);
                bool descHere = ((t & k) == 0);
                bool doSwap = descHere ? !aBetter : aBetter;
                if (doSwap) {
                    s[t] = c;  s[ixj] = a;
                    si[t] = ci; si[ixj] = ai;
                }
            }
            __syncthreads();
        }
    }
    if (t < KSEL) g_topk[b * KSEL + t] = si[t];
}

// ---------------------------------------------------------------------------
// K7: gather out[b, j, :] = x[b, topk[b][j], :]  (float4 vectorized)
// ---------------------------------------------------------------------------
__global__ void gather_kernel(const float* __restrict__ x,
                              float* __restrict__ out) {
    int row = blockIdx.x;
    int b = row >> 7, j = row & (KSEL - 1);
    int sidx = g_topk[b * KSEL + j];
    const float4* src = (const float4*)(x + ((size_t)b * SS + sidx) * CC);
    float4* dst = (float4*)(out + (size_t)row * CC);
    for (int c = threadIdx.x; c < CC / 4; c += blockDim.x) dst[c] = src[c];
}

// ---------------------------------------------------------------------------
extern "C" void kernel_launch(void* const* d_in, const int* in_sizes, int n_in,
                              void* d_out, int out_size) {
    const float* x    = (const float*)d_in[0];   // [32, 2048, 1536]
    const float* W    = (const float*)d_in[1];   // [200, 1536]
    const float* bias = (const float*)d_in[2];   // [200]
    float* out = (float*)d_out;                  // [32, 128, 1536]

    cudaFuncSetAttribute(score_mma_kernel,
                         cudaFuncAttributeMaxDynamicSharedMemorySize, SMEMB);

    wconv_kernel<<<(NCH16 * WCH1 + 255) / 256, 256>>>(W);
    score_mma_kernel<<<TOT / 128, 256, SMEMB>>>(x, bias);
    cand_kernel<<<BB, 1024>>>();
    exact_kernel<<<BB * (NCAND / CPB), 256>>>(x, W, bias);
    sort2_kernel<<<BB, 256>>>();
    gather_kernel<<<BB * KSEL, 256>>>(x, out);
}